// round 12
// baseline (speedup 1.0000x reference)
#include <cuda_runtime.h>
#include <cstdint>

// Shapes (fixed):
//   x [64,512,32,32] fp32 (HW=1024 contiguous)
//   router_weights [512,16], router_bias [16]
//   bn_gamma/beta [512], ln_gamma/beta [512]
// Output fp32: new_x [64,512] | logits [64,16] | probs [64,16]

#define B_DIM 64
#define C_DIM 512
#define A_DIM 16
#define HW    1024
#define EPSF  1e-5f
#define NBLK   296u    // 148 SMs * 2 blocks (96KB smem each) -> single wave
#define NWARP  2368u   // NBLK * 8
#define NTILE  32768u  // B*C tiles of 1024 floats
#define NSURV  64u
#define STAGES 3
#define STAGE_BYTES 4096
#define SMEM_DYN (8 * STAGES * STAGE_BYTES)   // 98304 B

__device__ float    g_sum[B_DIM * C_DIM];   // per-(b,c) spatial sum
__device__ float    g_csum[2][C_DIM];       // per-channel sum   (parity buffered)
__device__ float    g_csq [2][C_DIM];       // per-channel sumsq (parity buffered)
__device__ unsigned g_start = 0;            // start tickets (monotonic)
__device__ unsigned g_done  = 0;            // completion tickets (monotonic)

#define CP_ASYNC16(saddr, gptr) \
    asm volatile("cp.async.cg.shared.global [%0], [%1], 16;" \
                 :: "r"(saddr), "l"(gptr))
#define CP_COMMIT() asm volatile("cp.async.commit_group;")
#define CP_WAIT(n)  asm volatile("cp.async.wait_group %0;" :: "n"(n))

__global__ __launch_bounds__(256) void k_fused(
    const float* __restrict__ x,
    const float* __restrict__ rw,        // [512,16]
    const float* __restrict__ rbias,     // [16]
    const float* __restrict__ bng,
    const float* __restrict__ bnb,
    const float* __restrict__ lng,
    const float* __restrict__ lnb,
    float* __restrict__ out)
{
    extern __shared__ char dsm[];        // phase-1 staging; tail overlays it
    __shared__ float redG[8], redH[8];
    __shared__ float lsh[A_DIM];
    __shared__ float sG, sHb;
    __shared__ unsigned sstart, sdone;

    const int tid  = threadIdx.x;
    const int lane = tid & 31;
    const int wid  = tid >> 5;

    // ---------------- Launch parity (uniform: launches are serialized) ------
    if (tid == 0) sstart = atomicAdd(&g_start, 1u);
    __syncthreads();
    const unsigned par = (sstart / NBLK) & 1u;

    // ---------------- Phase 1: cp.async-pipelined spatial sums --------------
    {
        const unsigned w  = blockIdx.x * 8u + (unsigned)wid;
        const unsigned t0 = (w * NTILE) / NWARP;
        const unsigned t1 = ((w + 1u) * NTILE) / NWARP;
        const unsigned nt = t1 - t0;                     // 13 or 14

        char* wbuf = dsm + wid * (STAGES * STAGE_BYTES);
        const uint32_t sbase =
            (uint32_t)__cvta_generic_to_shared(wbuf) + (uint32_t)(lane * 16);
        const float4* gb = reinterpret_cast<const float4*>(x);

        // prologue: fill all stages
        const unsigned nis = (nt < (unsigned)STAGES) ? nt : (unsigned)STAGES;
#pragma unroll
        for (unsigned i = 0; i < (unsigned)STAGES; ++i) {
            if (i < nis) {
                const float4* g = gb + (size_t)(t0 + i) * 256 + lane;
                uint32_t s = sbase + i * STAGE_BYTES;
#pragma unroll
                for (int k = 0; k < 8; ++k) CP_ASYNC16(s + k * 512, g + k * 32);
                CP_COMMIT();
            }
        }

        int st = 0;
#pragma unroll 1
        for (unsigned i = 0; i < nt; ++i) {
            const unsigned rem = nt - i;
            if (rem > 2u)       { CP_WAIT(2); }
            else if (rem == 2u) { CP_WAIT(1); }
            else                { CP_WAIT(0); }

            // consume stage st (each thread reads exactly what it wrote)
            const float4* bufp = reinterpret_cast<const float4*>(
                wbuf + st * STAGE_BYTES) + lane;
            float s_ = 0.f, q_ = 0.f;
#pragma unroll
            for (int k = 0; k < 8; ++k) {
                float4 v = bufp[k * 32];
                s_ += v.x + v.y + v.z + v.w;
                q_ += v.x * v.x + v.y * v.y + v.z * v.z + v.w * v.w;
            }

            // reissue this stage for tile i+STAGES (FMAs above forced LDS
            // retirement, so the WAR on the stage is safe)
            if (i + STAGES < nt) {
                const float4* g = gb + (size_t)(t0 + i + STAGES) * 256 + lane;
                uint32_t s = sbase + st * STAGE_BYTES;
#pragma unroll
                for (int k = 0; k < 8; ++k) CP_ASYNC16(s + k * 512, g + k * 32);
                CP_COMMIT();
            }

#pragma unroll
            for (int o = 16; o; o >>= 1) {
                s_ += __shfl_xor_sync(0xFFFFFFFFu, s_, o);
                q_ += __shfl_xor_sync(0xFFFFFFFFu, q_, o);
            }
            if (lane == 0) {
                unsigned tile = t0 + i;                  // == b*512 + c
                unsigned c = tile & (C_DIM - 1u);
                g_sum[tile] = s_;
                atomicAdd(&g_csum[par][c], s_);          // RED (no return)
                atomicAdd(&g_csq [par][c], q_);
            }
            st = (st + 1 == STAGES) ? 0 : st + 1;
        }
    }

    // ---------------- Single ticket: wait for all phase-1 work --------------
    __threadfence();
    __syncthreads();
    if (tid == 0) sdone = atomicAdd(&g_done, 1u);
    __syncthreads();
    const unsigned old   = sdone;
    const unsigned idx   = old % NBLK;
    const unsigned dbase = old - idx;
    if (idx < NBLK - NSURV) return;                  // 232 blocks exit
    const int b = (int)(idx - (NBLK - NSURV));       // survivor -> batch row b

    if (tid == 0) {
        const unsigned target = dbase + NBLK;
        while ((int)(*(volatile unsigned*)&g_done - target) < 0) __nanosleep(32);
    }
    __syncthreads();
    __threadfence();                                  // acquire all phase-1 data

    // ---------------- Tail (overlays dead staging smem) ---------------------
    float* nxl     = reinterpret_cast<float*>(dsm);          // 512 floats
    float* part_pa = reinterpret_cast<float*>(dsm + 2048);   // 256
    float* part_sw = reinterpret_cast<float*>(dsm + 3072);   // 256
    float* part_sq = reinterpret_cast<float*>(dsm + 4096);   // 256

    {
        const int c0 = tid, c1 = tid + 256;
        const float invM  = 1.0f / (float)(B_DIM * HW);
        const float invHW = 1.0f / (float)HW;

        float mu0 = g_csum[par][c0] * invM;
        float mu1 = g_csum[par][c1] * invM;
        float r0  = rsqrtf(g_csq[par][c0] * invM - mu0 * mu0 + EPSF);
        float r1  = rsqrtf(g_csq[par][c1] * invM - mu1 * mu1 + EPSF);

        float n0 = bng[c0] * (g_sum[b * C_DIM + c0] * invHW - mu0) * r0 + bnb[c0];
        float n1 = bng[c1] * (g_sum[b * C_DIM + c1] * invHW - mu1) * r1 + bnb[c1];
        out[b * C_DIM + c0] = n0;
        out[b * C_DIM + c1] = n1;

        float lg0 = lng[c0], lg1 = lng[c1];
        nxl[c0] = n0 * lg0;  nxl[c1] = n1 * lg1;

        float gp = n0 * lg0 + n1 * lg1;
        float hp = n0 * lnb[c0] + n1 * lnb[c1];
#pragma unroll
        for (int o = 16; o; o >>= 1) {
            gp += __shfl_xor_sync(0xFFFFFFFFu, gp, o);
            hp += __shfl_xor_sync(0xFFFFFFFFu, hp, o);
        }
        if (lane == 0) { redG[wid] = gp; redH[wid] = hp; }
    }

    // Zero the other parity's accumulators for the next replay
    if (tid < 8) {
        g_csum[par ^ 1u][b * 8 + tid] = 0.f;
        g_csq [par ^ 1u][b * 8 + tid] = 0.f;
    }
    __syncthreads();
    if (tid == 0) {
        float g = 0.f, h = 0.f;
#pragma unroll
        for (int i = 0; i < 8; ++i) { g += redG[i]; h += redH[i]; }
        sG = g; sHb = h;
    }

    // Fused LN-weight + dot partials: thread (a = tid&15, grp = tid>>4)
    {
        const int a   = tid & 15;
        const int grp = tid >> 4;
        const float* wp  = rw  + (grp * 32) * A_DIM + a;
        const float* nlp = nxl + grp * 32;
        float pa = 0.f, sw = 0.f, sq = 0.f;
#pragma unroll
        for (int j = 0; j < 32; ++j) {
            float wv = wp[j * A_DIM];
            pa += nlp[j] * wv;
            sw += wv;
            sq += wv * wv;
        }
        part_pa[tid] = pa;  part_sw[tid] = sw;  part_sq[tid] = sq;
    }
    __syncthreads();

    // Logits + softmax
    float* logits_out = out + B_DIM * C_DIM;
    float* probs_out  = logits_out + B_DIM * A_DIM;

    if (tid < A_DIM) {
        float P = 0.f, SW = 0.f, SQ = 0.f;
#pragma unroll
        for (int g = 0; g < 16; ++g) {
            P  += part_pa[g * 16 + tid];
            SW += part_sw[g * 16 + tid];
            SQ += part_sq[g * 16 + tid];
        }
        const float invC = 1.0f / (float)C_DIM;
        float m    = SW * invC;
        float rstd = rsqrtf(SQ * invC - m * m + EPSF);
        float logit = rstd * (P - m * sG) + sHb + rbias[tid];
        lsh[tid] = logit;
        logits_out[b * A_DIM + tid] = logit;
    }
    __syncthreads();

    if (tid == 0) {
        float mx = lsh[0];
#pragma unroll
        for (int a = 1; a < A_DIM; ++a) mx = fmaxf(mx, lsh[a]);
        float e[A_DIM]; float ssum = 0.f;
#pragma unroll
        for (int a = 0; a < A_DIM; ++a) { e[a] = __expf(lsh[a] - mx); ssum += e[a]; }
        float inv = 1.0f / ssum;
#pragma unroll
        for (int a = 0; a < A_DIM; ++a) probs_out[b * A_DIM + a] = e[a] * inv;
    }
}

extern "C" void kernel_launch(void* const* d_in, const int* in_sizes, int n_in,
                              void* d_out, int out_size)
{
    const float* x        = (const float*)d_in[0];
    const float* rw       = (const float*)d_in[1];
    const float* rbias    = (const float*)d_in[2];
    const float* bn_gamma = (const float*)d_in[3];
    const float* bn_beta  = (const float*)d_in[4];
    const float* ln_gamma = (const float*)d_in[5];
    const float* ln_beta  = (const float*)d_in[6];

    cudaFuncSetAttribute(k_fused, cudaFuncAttributeMaxDynamicSharedMemorySize,
                         SMEM_DYN);
    k_fused<<<NBLK, 256, SMEM_DYN>>>(x, rw, rbias, bn_gamma, bn_beta,
                                     ln_gamma, ln_beta, (float*)d_out);
}